// round 13
// baseline (speedup 1.0000x reference)
#include <cuda_runtime.h>
#include <cuda_fp16.h>
#include <cstdint>

// x (256,18,18,512) f32, W (18,512,512) f32, b (18,512) f32, idx (18) i32
#define KB_   256
#define O_    18
#define J_    18
#define DIM   512
#define M_TOTAL (KB_ * J_)        // 4608
#define BM    128
#define BN    128
#define BKH   64                  // k elements per tile (fp16)
#define ST2   72                  // smem row stride in halves: 64 + 8 pad
#define NKT   (DIM / BKH)         // 8
#define STAGES 3
#define NTHREADS 256
#define SCALE_F 0.044194173824159216f

#define SA_H  (BM * ST2)                    // 9216 halves
#define STG_H (2 * SA_H)                    // 18432 halves = 36864 B
#define SMEM_BYTES (STAGES * STG_H * 2)     // 110592

#define W_ELEMS (O_ * DIM * DIM)            // 4718592

__device__ int g_sel[J_];
__device__ uint4 g_Wh4[W_ELEMS / 8];        // W as fp16 (8 halves per uint4)

__global__ void prep_kernel(const float* __restrict__ W, const int* __restrict__ idx, int n) {
    if (blockIdx.x == 0 && threadIdx.x < 32) {
        int t = threadIdx.x;
        if (t < J_) g_sel[t] = 0;
        __syncwarp();
        if (t < n) {
            int v = idx[t];
            if (v >= 0 && v < J_) g_sel[v] = 1;
        }
    }
    const int nw = W_ELEMS / 8;
    for (int i = blockIdx.x * blockDim.x + threadIdx.x; i < nw;
         i += gridDim.x * blockDim.x) {
        float4 a = reinterpret_cast<const float4*>(W)[2 * i];
        float4 b = reinterpret_cast<const float4*>(W)[2 * i + 1];
        __half2 h0 = __floats2half2_rn(a.x, a.y);
        __half2 h1 = __floats2half2_rn(a.z, a.w);
        __half2 h2 = __floats2half2_rn(b.x, b.y);
        __half2 h3 = __floats2half2_rn(b.z, b.w);
        uint4 u;
        u.x = *reinterpret_cast<uint32_t*>(&h0);
        u.y = *reinterpret_cast<uint32_t*>(&h1);
        u.z = *reinterpret_cast<uint32_t*>(&h2);
        u.w = *reinterpret_cast<uint32_t*>(&h3);
        g_Wh4[i] = u;
    }
}

__device__ __forceinline__ uint32_t smem_u32(const void* p) {
    uint32_t a;
    asm("{ .reg .u64 t; cvta.to.shared.u64 t, %1; cvt.u32.u64 %0, t; }" : "=r"(a) : "l"(p));
    return a;
}

__device__ __forceinline__ void cp16(uint32_t dst, const void* src) {
    asm volatile("cp.async.cg.shared.global [%0], [%1], 16;" :: "r"(dst), "l"(src));
}

__device__ __forceinline__ void ldsm_x4(uint32_t* r, uint32_t addr) {
    asm volatile("ldmatrix.sync.aligned.m8n8.x4.shared.b16 {%0,%1,%2,%3}, [%4];"
                 : "=r"(r[0]), "=r"(r[1]), "=r"(r[2]), "=r"(r[3]) : "r"(addr));
}

__device__ __forceinline__ void mma_f16(float* acc, const uint32_t* a, const uint32_t* b) {
    asm volatile(
        "mma.sync.aligned.m16n8k16.row.col.f32.f16.f16.f32 "
        "{%0,%1,%2,%3}, {%4,%5,%6,%7}, {%8,%9}, {%0,%1,%2,%3};\n"
        : "+f"(acc[0]), "+f"(acc[1]), "+f"(acc[2]), "+f"(acc[3])
        : "r"(a[0]), "r"(a[1]), "r"(a[2]), "r"(a[3]), "r"(b[0]), "r"(b[1]));
}

// load 8 fp32, convert RN to 8 halves, store one uint4 to smem
__device__ __forceinline__ void cvt_store8(const float* src, __half* dst) {
    float4 a = *reinterpret_cast<const float4*>(src);
    float4 b = *reinterpret_cast<const float4*>(src + 4);
    __half2 h0 = __floats2half2_rn(a.x, a.y);
    __half2 h1 = __floats2half2_rn(a.z, a.w);
    __half2 h2 = __floats2half2_rn(b.x, b.y);
    __half2 h3 = __floats2half2_rn(b.z, b.w);
    uint4 u;
    u.x = *reinterpret_cast<uint32_t*>(&h0);
    u.y = *reinterpret_cast<uint32_t*>(&h1);
    u.z = *reinterpret_cast<uint32_t*>(&h2);
    u.w = *reinterpret_cast<uint32_t*>(&h3);
    *reinterpret_cast<uint4*>(dst) = u;
}

__global__ __launch_bounds__(NTHREADS, 2)
void dirnet_gemm_kernel(const float* __restrict__ x, const float* __restrict__ bias,
                        float* __restrict__ out) {
    extern __shared__ __half smh[];
    const uint32_t smb = smem_u32(smh);
    const __half* wh = reinterpret_cast<const __half*>(g_Wh4);

    const int o   = blockIdx.z;
    const int mt  = blockIdx.y;
    const int nt  = blockIdx.x;
    const int tid = threadIdx.x;
    const int lane = tid & 31;
    const int wid  = tid >> 5;          // 0..7
    const int g  = lane >> 2;           // 0..7
    const int t4 = lane & 3;            // 0..3
    const int wm = wid >> 2;            // 0..1 -> 64 rows
    const int wn = wid & 3;             // 0..3 -> 32 cols
    const int mBase = wm * 64;
    const int nBase = wn * 32;

    // ---- producer addressing: per thread 4 slots of 8 halves for A and for B ----
    // slot f = tid + it*256 : row = f>>3 (0..127), c8 = f&7
    int aSrc[4], bSrc[4];               // element offsets; + kt*BKH at use
    uint32_t tAOffH[4];                 // half offsets within a stage (A)
    uint32_t tBOff[4];                  // byte offsets within a stage (B)
    #pragma unroll
    for (int it = 0; it < 4; it++) {
        int f   = tid + it * 256;
        int row = f >> 3;
        int c8  = f & 7;
        int m   = mt * BM + row;
        int kb  = m / J_;
        int j   = m - kb * J_;
        aSrc[it]  = ((kb * O_ + o) * J_ + j) * DIM + c8 * 8;     // fp32 elements
        bSrc[it]  = o * (DIM * DIM) + (nt * BN + row) * DIM + c8 * 8;  // fp16 elements
        tAOffH[it] = (uint32_t)(row * ST2 + c8 * 8);
        tBOff[it]  = (uint32_t)((SA_H + row * ST2 + c8 * 8) * 2);
    }

    // ---- ldmatrix per-thread addresses (byte offsets within a stage) ----
    const int r8  = lane & 7;
    const int seg = lane >> 3;          // 0..3
    uint32_t ofA[4], ofB[2];
    #pragma unroll
    for (int mf = 0; mf < 4; mf++)
        ofA[mf] = (uint32_t)(((mBase + mf * 16 + (seg & 1) * 8 + r8) * ST2
                              + (seg >> 1) * 8) * 2);
    #pragma unroll
    for (int p = 0; p < 2; p++)
        ofB[p] = (uint32_t)((SA_H + (nBase + (2 * p + (seg >> 1)) * 8 + r8) * ST2
                             + (seg & 1) * 8) * 2);

    // ---- prologue: stages 0,1 (B cp.async, A LDG->cvt->STS) ----
    #pragma unroll
    for (int s = 0; s < 2; s++) {
        uint32_t base = smb + s * STG_H * 2;
        __half* sA = smh + s * STG_H;
        #pragma unroll
        for (int it = 0; it < 4; it++) {
            cp16(base + tBOff[it], wh + bSrc[it] + s * BKH);
            cvt_store8(x + aSrc[it] + s * BKH, sA + tAOffH[it]);
        }
        asm volatile("cp.async.commit_group;" ::: "memory");
    }

    float acc[4][4][4];
    #pragma unroll
    for (int a = 0; a < 4; a++)
        #pragma unroll
        for (int b = 0; b < 4; b++)
            #pragma unroll
            for (int c = 0; c < 4; c++) acc[a][b][c] = 0.f;

    for (int kt = 0; kt < NKT; kt++) {
        const int cur = kt % STAGES;
        asm volatile("cp.async.wait_group 1;" ::: "memory");
        __syncthreads();

        const uint32_t sbase = smb + cur * STG_H * 2;

        // ---- kstep 0 first: tensor pipe starts immediately ----
        {
            uint32_t af[4][4], bf[2][4];
            #pragma unroll
            for (int mf = 0; mf < 4; mf++) ldsm_x4(af[mf], sbase + ofA[mf]);
            #pragma unroll
            for (int p = 0; p < 2; p++)   ldsm_x4(bf[p], sbase + ofB[p]);
            #pragma unroll
            for (int mf = 0; mf < 4; mf++)
                #pragma unroll
                for (int nf = 0; nf < 4; nf++)
                    mma_f16(acc[mf][nf], af[mf], &bf[nf >> 1][(nf & 1) * 2]);
        }

        // ---- producer for stage kt+2, overlapped with ksteps 1-3 ----
        if (kt + 2 < NKT) {
            const int nxt = (kt + 2) % STAGES;
            uint32_t base = smb + nxt * STG_H * 2;
            __half* sA = smh + nxt * STG_H;
            #pragma unroll
            for (int it = 0; it < 4; it++)
                cp16(base + tBOff[it], wh + bSrc[it] + (kt + 2) * BKH);
            #pragma unroll
            for (int it = 0; it < 4; it++)
                cvt_store8(x + aSrc[it] + (kt + 2) * BKH, sA + tAOffH[it]);
        }
        asm volatile("cp.async.commit_group;" ::: "memory");

        // ---- ksteps 1-3 ----
        #pragma unroll
        for (int ks = 1; ks < 4; ks++) {
            const uint32_t kadd = (uint32_t)(ks * 32);   // 16 halves = 32 B per kstep
            uint32_t af[4][4], bf[2][4];
            #pragma unroll
            for (int mf = 0; mf < 4; mf++) ldsm_x4(af[mf], sbase + ofA[mf] + kadd);
            #pragma unroll
            for (int p = 0; p < 2; p++)   ldsm_x4(bf[p], sbase + ofB[p] + kadd);
            #pragma unroll
            for (int mf = 0; mf < 4; mf++)
                #pragma unroll
                for (int nf = 0; nf < 4; nf++)
                    mma_f16(acc[mf][nf], af[mf], &bf[nf >> 1][(nf & 1) * 2]);
        }
    }

    // ---- epilogue ----
    const float* bRow = bias + o * DIM;
    #pragma unroll
    for (int mf = 0; mf < 4; mf++) {
        #pragma unroll
        for (int half = 0; half < 2; half++) {
            int mloc = mBase + mf * 16 + g + half * 8;
            int m  = mt * BM + mloc;
            int kb = m / J_;
            int j  = m - kb * J_;
            int rowOff = ((kb * O_ + o) * J_ + j) * DIM;
            int selv = g_sel[j];
            #pragma unroll
            for (int nf = 0; nf < 4; nf++) {
                int n = nt * BN + nBase + nf * 8 + t4 * 2;
                float v0, v1;
                if (selv) {
                    v0 = acc[mf][nf][half * 2 + 0] * SCALE_F + bRow[n];
                    v1 = acc[mf][nf][half * 2 + 1] * SCALE_F + bRow[n + 1];
                } else {
                    v0 = x[rowOff + n];
                    v1 = x[rowOff + n + 1];
                }
                *reinterpret_cast<float2*>(out + rowOff + n) = make_float2(v0, v1);
            }
        }
    }
}

extern "C" void kernel_launch(void* const* d_in, const int* in_sizes, int n_in,
                              void* d_out, int out_size) {
    const float* x   = (const float*)d_in[0];
    const float* W   = (const float*)d_in[1];
    const float* b   = (const float*)d_in[2];
    const int*   idx = (const int*)d_in[3];
    float* out = (float*)d_out;

    prep_kernel<<<512, 256>>>(W, idx, in_sizes[3]);

    cudaFuncSetAttribute(dirnet_gemm_kernel,
                         cudaFuncAttributeMaxDynamicSharedMemorySize, SMEM_BYTES);

    dim3 grid(DIM / BN, M_TOTAL / BM, O_);
    dirnet_gemm_kernel<<<grid, NTHREADS, SMEM_BYTES>>>(x, b, out);
}

// round 14
// speedup vs baseline: 1.0039x; 1.0039x over previous
#include <cuda_runtime.h>
#include <cuda_fp16.h>
#include <cstdint>

// x (256,18,18,512) f32, W (18,512,512) f32, b (18,512) f32, idx (18) i32
#define KB_   256
#define O_    18
#define J_    18
#define DIM   512
#define M_TOTAL (KB_ * J_)        // 4608
#define BM    128
#define BN    128
#define BKH   64                  // k elements per tile (fp16)
#define ST2   72                  // smem row stride in halves: 64 + 8 pad
#define NKT   (DIM / BKH)         // 8
#define STAGES 3
#define NTHREADS 256
#define SCALE_F 0.044194173824159216f

#define SA_H  (BM * ST2)                    // 9216 halves
#define STG_H (2 * SA_H)                    // 18432 halves = 36864 B
#define SMEM_BYTES (STAGES * STG_H * 2)     // 110592

#define W_ELEMS (O_ * DIM * DIM)            // 4718592

__device__ int g_sel[J_];
__device__ uint4 g_Wh4[W_ELEMS / 8];        // W as fp16 (8 halves per uint4)

__global__ void prep_kernel(const float* __restrict__ W, const int* __restrict__ idx, int n) {
    if (blockIdx.x == 0 && threadIdx.x < 32) {
        int t = threadIdx.x;
        if (t < J_) g_sel[t] = 0;
        __syncwarp();
        if (t < n) {
            int v = idx[t];
            if (v >= 0 && v < J_) g_sel[v] = 1;
        }
    }
    const int nw = W_ELEMS / 8;
    for (int i = blockIdx.x * blockDim.x + threadIdx.x; i < nw;
         i += gridDim.x * blockDim.x) {
        float4 a = reinterpret_cast<const float4*>(W)[2 * i];
        float4 b = reinterpret_cast<const float4*>(W)[2 * i + 1];
        __half2 h0 = __floats2half2_rn(a.x, a.y);
        __half2 h1 = __floats2half2_rn(a.z, a.w);
        __half2 h2 = __floats2half2_rn(b.x, b.y);
        __half2 h3 = __floats2half2_rn(b.z, b.w);
        uint4 u;
        u.x = *reinterpret_cast<uint32_t*>(&h0);
        u.y = *reinterpret_cast<uint32_t*>(&h1);
        u.z = *reinterpret_cast<uint32_t*>(&h2);
        u.w = *reinterpret_cast<uint32_t*>(&h3);
        g_Wh4[i] = u;
    }
}

__device__ __forceinline__ uint32_t smem_u32(const void* p) {
    uint32_t a;
    asm("{ .reg .u64 t; cvta.to.shared.u64 t, %1; cvt.u32.u64 %0, t; }" : "=r"(a) : "l"(p));
    return a;
}

__device__ __forceinline__ void cp16(uint32_t dst, const void* src) {
    asm volatile("cp.async.cg.shared.global [%0], [%1], 16;" :: "r"(dst), "l"(src));
}

__device__ __forceinline__ void ldsm_x4(uint32_t* r, uint32_t addr) {
    asm volatile("ldmatrix.sync.aligned.m8n8.x4.shared.b16 {%0,%1,%2,%3}, [%4];"
                 : "=r"(r[0]), "=r"(r[1]), "=r"(r[2]), "=r"(r[3]) : "r"(addr));
}

__device__ __forceinline__ void mma_f16(float* acc, const uint32_t* a, const uint32_t* b) {
    asm volatile(
        "mma.sync.aligned.m16n8k16.row.col.f32.f16.f16.f32 "
        "{%0,%1,%2,%3}, {%4,%5,%6,%7}, {%8,%9}, {%0,%1,%2,%3};\n"
        : "+f"(acc[0]), "+f"(acc[1]), "+f"(acc[2]), "+f"(acc[3])
        : "r"(a[0]), "r"(a[1]), "r"(a[2]), "r"(a[3]), "r"(b[0]), "r"(b[1]));
}

// load 8 fp32, convert RN to 8 halves, store one uint4 to smem
__device__ __forceinline__ void cvt_store8(const float* src, __half* dst) {
    float4 a = *reinterpret_cast<const float4*>(src);
    float4 b = *reinterpret_cast<const float4*>(src + 4);
    __half2 h0 = __floats2half2_rn(a.x, a.y);
    __half2 h1 = __floats2half2_rn(a.z, a.w);
    __half2 h2 = __floats2half2_rn(b.x, b.y);
    __half2 h3 = __floats2half2_rn(b.z, b.w);
    uint4 u;
    u.x = *reinterpret_cast<uint32_t*>(&h0);
    u.y = *reinterpret_cast<uint32_t*>(&h1);
    u.z = *reinterpret_cast<uint32_t*>(&h2);
    u.w = *reinterpret_cast<uint32_t*>(&h3);
    *reinterpret_cast<uint4*>(dst) = u;
}

__global__ __launch_bounds__(NTHREADS, 2)
void dirnet_gemm_kernel(const float* __restrict__ x, const float* __restrict__ bias,
                        float* __restrict__ out) {
    extern __shared__ __half smh[];
    const uint32_t smb = smem_u32(smh);
    const __half* wh = reinterpret_cast<const __half*>(g_Wh4);

    const int o   = blockIdx.z;
    const int mt  = blockIdx.y;
    const int nt  = blockIdx.x;
    const int tid = threadIdx.x;
    const int lane = tid & 31;
    const int wid  = tid >> 5;          // 0..7
    const int g  = lane >> 2;           // 0..7
    const int t4 = lane & 3;            // 0..3
    const int wm = wid >> 2;            // 0..1 -> 64 rows
    const int wn = wid & 3;             // 0..3 -> 32 cols
    const int mBase = wm * 64;
    const int nBase = wn * 32;

    // ---- producer addressing: per thread 4 slots of 8 halves for A and for B ----
    // slot f = tid + it*256 : row = f>>3 (0..127), c8 = f&7
    int aSrc[4], bSrc[4];               // element offsets; + kt*BKH at use
    uint32_t tAOffH[4];                 // half offsets within a stage (A)
    uint32_t tBOff[4];                  // byte offsets within a stage (B)
    #pragma unroll
    for (int it = 0; it < 4; it++) {
        int f   = tid + it * 256;
        int row = f >> 3;
        int c8  = f & 7;
        int m   = mt * BM + row;
        int kb  = m / J_;
        int j   = m - kb * J_;
        aSrc[it]  = ((kb * O_ + o) * J_ + j) * DIM + c8 * 8;     // fp32 elements
        bSrc[it]  = o * (DIM * DIM) + (nt * BN + row) * DIM + c8 * 8;  // fp16 elements
        tAOffH[it] = (uint32_t)(row * ST2 + c8 * 8);
        tBOff[it]  = (uint32_t)((SA_H + row * ST2 + c8 * 8) * 2);
    }

    // ---- ldmatrix per-thread addresses (byte offsets within a stage) ----
    const int r8  = lane & 7;
    const int seg = lane >> 3;          // 0..3
    uint32_t ofA[4], ofB[2];
    #pragma unroll
    for (int mf = 0; mf < 4; mf++)
        ofA[mf] = (uint32_t)(((mBase + mf * 16 + (seg & 1) * 8 + r8) * ST2
                              + (seg >> 1) * 8) * 2);
    #pragma unroll
    for (int p = 0; p < 2; p++)
        ofB[p] = (uint32_t)((SA_H + (nBase + (2 * p + (seg >> 1)) * 8 + r8) * ST2
                             + (seg & 1) * 8) * 2);

    // ---- prologue: stages 0,1 (B cp.async, A LDG->cvt->STS) ----
    #pragma unroll
    for (int s = 0; s < 2; s++) {
        uint32_t base = smb + s * STG_H * 2;
        __half* sA = smh + s * STG_H;
        #pragma unroll
        for (int it = 0; it < 4; it++) {
            cp16(base + tBOff[it], wh + bSrc[it] + s * BKH);
            cvt_store8(x + aSrc[it] + s * BKH, sA + tAOffH[it]);
        }
        asm volatile("cp.async.commit_group;" ::: "memory");
    }

    float acc[4][4][4];
    #pragma unroll
    for (int a = 0; a < 4; a++)
        #pragma unroll
        for (int b = 0; b < 4; b++)
            #pragma unroll
            for (int c = 0; c < 4; c++) acc[a][b][c] = 0.f;

    for (int kt = 0; kt < NKT; kt++) {
        const int cur = kt % STAGES;
        asm volatile("cp.async.wait_group 1;" ::: "memory");
        __syncthreads();

        const uint32_t sbase = smb + cur * STG_H * 2;

        // ---- kstep 0 first: tensor pipe starts immediately ----
        {
            uint32_t af[4][4], bf[2][4];
            #pragma unroll
            for (int mf = 0; mf < 4; mf++) ldsm_x4(af[mf], sbase + ofA[mf]);
            #pragma unroll
            for (int p = 0; p < 2; p++)   ldsm_x4(bf[p], sbase + ofB[p]);
            #pragma unroll
            for (int mf = 0; mf < 4; mf++)
                #pragma unroll
                for (int nf = 0; nf < 4; nf++)
                    mma_f16(acc[mf][nf], af[mf], &bf[nf >> 1][(nf & 1) * 2]);
        }

        // ---- producer for stage kt+2, overlapped with ksteps 1-3 ----
        if (kt + 2 < NKT) {
            const int nxt = (kt + 2) % STAGES;
            uint32_t base = smb + nxt * STG_H * 2;
            __half* sA = smh + nxt * STG_H;
            #pragma unroll
            for (int it = 0; it < 4; it++)
                cp16(base + tBOff[it], wh + bSrc[it] + (kt + 2) * BKH);
            #pragma unroll
            for (int it = 0; it < 4; it++)
                cvt_store8(x + aSrc[it] + (kt + 2) * BKH, sA + tAOffH[it]);
        }
        asm volatile("cp.async.commit_group;" ::: "memory");

        // ---- ksteps 1-3 ----
        #pragma unroll
        for (int ks = 1; ks < 4; ks++) {
            const uint32_t kadd = (uint32_t)(ks * 32);   // 16 halves = 32 B per kstep
            uint32_t af[4][4], bf[2][4];
            #pragma unroll
            for (int mf = 0; mf < 4; mf++) ldsm_x4(af[mf], sbase + ofA[mf] + kadd);
            #pragma unroll
            for (int p = 0; p < 2; p++)   ldsm_x4(bf[p], sbase + ofB[p] + kadd);
            #pragma unroll
            for (int mf = 0; mf < 4; mf++)
                #pragma unroll
                for (int nf = 0; nf < 4; nf++)
                    mma_f16(acc[mf][nf], af[mf], &bf[nf >> 1][(nf & 1) * 2]);
        }
    }

    // ---- epilogue ----
    const float* bRow = bias + o * DIM;
    #pragma unroll
    for (int mf = 0; mf < 4; mf++) {
        #pragma unroll
        for (int half = 0; half < 2; half++) {
            int mloc = mBase + mf * 16 + g + half * 8;
            int m  = mt * BM + mloc;
            int kb = m / J_;
            int j  = m - kb * J_;
            int rowOff = ((kb * O_ + o) * J_ + j) * DIM;
            int selv = g_sel[j];
            #pragma unroll
            for (int nf = 0; nf < 4; nf++) {
                int n = nt * BN + nBase + nf * 8 + t4 * 2;
                float v0, v1;
                if (selv) {
                    v0 = acc[mf][nf][half * 2 + 0] * SCALE_F + bRow[n];
                    v1 = acc[mf][nf][half * 2 + 1] * SCALE_F + bRow[n + 1];
                } else {
                    v0 = x[rowOff + n];
                    v1 = x[rowOff + n + 1];
                }
                *reinterpret_cast<float2*>(out + rowOff + n) = make_float2(v0, v1);
            }
        }
    }
}

extern "C" void kernel_launch(void* const* d_in, const int* in_sizes, int n_in,
                              void* d_out, int out_size) {
    const float* x   = (const float*)d_in[0];
    const float* W   = (const float*)d_in[1];
    const float* b   = (const float*)d_in[2];
    const int*   idx = (const int*)d_in[3];
    float* out = (float*)d_out;

    prep_kernel<<<512, 256>>>(W, idx, in_sizes[3]);

    cudaFuncSetAttribute(dirnet_gemm_kernel,
                         cudaFuncAttributeMaxDynamicSharedMemorySize, SMEM_BYTES);

    dim3 grid(DIM / BN, M_TOTAL / BM, O_);
    dirnet_gemm_kernel<<<grid, NTHREADS, SMEM_BYTES>>>(x, b, out);
}

// round 15
// speedup vs baseline: 1.0059x; 1.0020x over previous
#include <cuda_runtime.h>
#include <cuda_fp16.h>
#include <cstdint>

// x (256,18,18,512) f32, W (18,512,512) f32, b (18,512) f32, idx (18) i32
#define KB_   256
#define O_    18
#define J_    18
#define DIM   512
#define M_TOTAL (KB_ * J_)        // 4608
#define BM    128
#define BN    128
#define BKH   64                  // k elements per tile (fp16)
#define ST2   72                  // smem row stride in halves: 64 + 8 pad
#define NKT   (DIM / BKH)         // 8
#define STAGES 3
#define NTHREADS 256
#define SCALE_F 0.044194173824159216f

#define SA_H  (BM * ST2)                    // 9216 halves
#define STG_H (2 * SA_H)                    // 18432 halves = 36864 B
#define SMEM_BYTES (STAGES * STG_H * 2)     // 110592

#define W_ELEMS (O_ * DIM * DIM)            // 4718592

__device__ int g_sel[J_];
__device__ uint4 g_Wh4[W_ELEMS / 8];        // W as fp16 (8 halves per uint4)

__global__ void prep_kernel(const float* __restrict__ W, const int* __restrict__ idx, int n) {
    if (blockIdx.x == 0 && threadIdx.x < 32) {
        int t = threadIdx.x;
        if (t < J_) g_sel[t] = 0;
        __syncwarp();
        if (t < n) {
            int v = idx[t];
            if (v >= 0 && v < J_) g_sel[v] = 1;
        }
    }
    const int nw = W_ELEMS / 8;
    for (int i = blockIdx.x * blockDim.x + threadIdx.x; i < nw;
         i += gridDim.x * blockDim.x) {
        float4 a = reinterpret_cast<const float4*>(W)[2 * i];
        float4 b = reinterpret_cast<const float4*>(W)[2 * i + 1];
        __half2 h0 = __floats2half2_rn(a.x, a.y);
        __half2 h1 = __floats2half2_rn(a.z, a.w);
        __half2 h2 = __floats2half2_rn(b.x, b.y);
        __half2 h3 = __floats2half2_rn(b.z, b.w);
        uint4 u;
        u.x = *reinterpret_cast<uint32_t*>(&h0);
        u.y = *reinterpret_cast<uint32_t*>(&h1);
        u.z = *reinterpret_cast<uint32_t*>(&h2);
        u.w = *reinterpret_cast<uint32_t*>(&h3);
        g_Wh4[i] = u;
    }
}

__device__ __forceinline__ uint32_t smem_u32(const void* p) {
    uint32_t a;
    asm("{ .reg .u64 t; cvta.to.shared.u64 t, %1; cvt.u32.u64 %0, t; }" : "=r"(a) : "l"(p));
    return a;
}

__device__ __forceinline__ void cp16(uint32_t dst, const void* src) {
    asm volatile("cp.async.cg.shared.global [%0], [%1], 16;" :: "r"(dst), "l"(src));
}

__device__ __forceinline__ void ldsm_x4(uint32_t* r, uint32_t addr) {
    asm volatile("ldmatrix.sync.aligned.m8n8.x4.shared.b16 {%0,%1,%2,%3}, [%4];"
                 : "=r"(r[0]), "=r"(r[1]), "=r"(r[2]), "=r"(r[3]) : "r"(addr));
}

__device__ __forceinline__ void mma_f16(float* acc, const uint32_t* a, const uint32_t* b) {
    asm volatile(
        "mma.sync.aligned.m16n8k16.row.col.f32.f16.f16.f32 "
        "{%0,%1,%2,%3}, {%4,%5,%6,%7}, {%8,%9}, {%0,%1,%2,%3};\n"
        : "+f"(acc[0]), "+f"(acc[1]), "+f"(acc[2]), "+f"(acc[3])
        : "r"(a[0]), "r"(a[1]), "r"(a[2]), "r"(a[3]), "r"(b[0]), "r"(b[1]));
}

// load 8 fp32, convert RN to 8 halves, store one uint4 to smem
__device__ __forceinline__ void cvt_store8(const float* src, __half* dst) {
    float4 a = *reinterpret_cast<const float4*>(src);
    float4 b = *reinterpret_cast<const float4*>(src + 4);
    __half2 h0 = __floats2half2_rn(a.x, a.y);
    __half2 h1 = __floats2half2_rn(a.z, a.w);
    __half2 h2 = __floats2half2_rn(b.x, b.y);
    __half2 h3 = __floats2half2_rn(b.z, b.w);
    uint4 u;
    u.x = *reinterpret_cast<uint32_t*>(&h0);
    u.y = *reinterpret_cast<uint32_t*>(&h1);
    u.z = *reinterpret_cast<uint32_t*>(&h2);
    u.w = *reinterpret_cast<uint32_t*>(&h3);
    *reinterpret_cast<uint4*>(dst) = u;
}

__global__ __launch_bounds__(NTHREADS, 2)
void dirnet_gemm_kernel(const float* __restrict__ x, const float* __restrict__ bias,
                        float* __restrict__ out) {
    extern __shared__ __half smh[];
    const uint32_t smb = smem_u32(smh);
    const __half* wh = reinterpret_cast<const __half*>(g_Wh4);

    const int o   = blockIdx.z;
    const int mt  = blockIdx.y;
    const int nt  = blockIdx.x;
    const int tid = threadIdx.x;
    const int lane = tid & 31;
    const int wid  = tid >> 5;          // 0..7
    const int g  = lane >> 2;           // 0..7
    const int t4 = lane & 3;            // 0..3
    const int wm = wid >> 2;            // 0..1 -> 64 rows
    const int wn = wid & 3;             // 0..3 -> 32 cols
    const int mBase = wm * 64;
    const int nBase = wn * 32;

    // ---- producer addressing: per thread 4 slots of 8 halves for A and for B ----
    // slot f = tid + it*256 : row = f>>3 (0..127), c8 = f&7
    int aSrc[4], bSrc[4];               // element offsets; + kt*BKH at use
    uint32_t tAOffH[4];                 // half offsets within a stage (A)
    uint32_t tBOff[4];                  // byte offsets within a stage (B)
    #pragma unroll
    for (int it = 0; it < 4; it++) {
        int f   = tid + it * 256;
        int row = f >> 3;
        int c8  = f & 7;
        int m   = mt * BM + row;
        int kb  = m / J_;
        int j   = m - kb * J_;
        aSrc[it]  = ((kb * O_ + o) * J_ + j) * DIM + c8 * 8;     // fp32 elements
        bSrc[it]  = o * (DIM * DIM) + (nt * BN + row) * DIM + c8 * 8;  // fp16 elements
        tAOffH[it] = (uint32_t)(row * ST2 + c8 * 8);
        tBOff[it]  = (uint32_t)((SA_H + row * ST2 + c8 * 8) * 2);
    }

    // ---- ldmatrix per-thread addresses (byte offsets within a stage) ----
    const int r8  = lane & 7;
    const int seg = lane >> 3;          // 0..3
    uint32_t ofA[4], ofB[2];
    #pragma unroll
    for (int mf = 0; mf < 4; mf++)
        ofA[mf] = (uint32_t)(((mBase + mf * 16 + (seg & 1) * 8 + r8) * ST2
                              + (seg >> 1) * 8) * 2);
    #pragma unroll
    for (int p = 0; p < 2; p++)
        ofB[p] = (uint32_t)((SA_H + (nBase + (2 * p + (seg >> 1)) * 8 + r8) * ST2
                             + (seg & 1) * 8) * 2);

    // ---- prologue: stages 0,1 (B cp.async, A LDG->cvt->STS) ----
    #pragma unroll
    for (int s = 0; s < 2; s++) {
        uint32_t base = smb + s * STG_H * 2;
        __half* sA = smh + s * STG_H;
        #pragma unroll
        for (int it = 0; it < 4; it++) {
            cp16(base + tBOff[it], wh + bSrc[it] + s * BKH);
            cvt_store8(x + aSrc[it] + s * BKH, sA + tAOffH[it]);
        }
        asm volatile("cp.async.commit_group;" ::: "memory");
    }

    float acc[4][4][4];
    #pragma unroll
    for (int a = 0; a < 4; a++)
        #pragma unroll
        for (int b = 0; b < 4; b++)
            #pragma unroll
            for (int c = 0; c < 4; c++) acc[a][b][c] = 0.f;

    for (int kt = 0; kt < NKT; kt++) {
        const int cur = kt % STAGES;
        asm volatile("cp.async.wait_group 1;" ::: "memory");
        __syncthreads();

        const uint32_t sbase = smb + cur * STG_H * 2;

        // ---- kstep 0 first: tensor pipe starts immediately ----
        {
            uint32_t af[4][4], bf[2][4];
            #pragma unroll
            for (int mf = 0; mf < 4; mf++) ldsm_x4(af[mf], sbase + ofA[mf]);
            #pragma unroll
            for (int p = 0; p < 2; p++)   ldsm_x4(bf[p], sbase + ofB[p]);
            #pragma unroll
            for (int mf = 0; mf < 4; mf++)
                #pragma unroll
                for (int nf = 0; nf < 4; nf++)
                    mma_f16(acc[mf][nf], af[mf], &bf[nf >> 1][(nf & 1) * 2]);
        }

        // ---- producer for stage kt+2, overlapped with ksteps 1-3 ----
        if (kt + 2 < NKT) {
            const int nxt = (kt + 2) % STAGES;
            uint32_t base = smb + nxt * STG_H * 2;
            __half* sA = smh + nxt * STG_H;
            #pragma unroll
            for (int it = 0; it < 4; it++)
                cp16(base + tBOff[it], wh + bSrc[it] + (kt + 2) * BKH);
            #pragma unroll
            for (int it = 0; it < 4; it++)
                cvt_store8(x + aSrc[it] + (kt + 2) * BKH, sA + tAOffH[it]);
        }
        asm volatile("cp.async.commit_group;" ::: "memory");

        // ---- ksteps 1-3 ----
        #pragma unroll
        for (int ks = 1; ks < 4; ks++) {
            const uint32_t kadd = (uint32_t)(ks * 32);   // 16 halves = 32 B per kstep
            uint32_t af[4][4], bf[2][4];
            #pragma unroll
            for (int mf = 0; mf < 4; mf++) ldsm_x4(af[mf], sbase + ofA[mf] + kadd);
            #pragma unroll
            for (int p = 0; p < 2; p++)   ldsm_x4(bf[p], sbase + ofB[p] + kadd);
            #pragma unroll
            for (int mf = 0; mf < 4; mf++)
                #pragma unroll
                for (int nf = 0; nf < 4; nf++)
                    mma_f16(acc[mf][nf], af[mf], &bf[nf >> 1][(nf & 1) * 2]);
        }
    }

    // ---- epilogue ----
    const float* bRow = bias + o * DIM;
    #pragma unroll
    for (int mf = 0; mf < 4; mf++) {
        #pragma unroll
        for (int half = 0; half < 2; half++) {
            int mloc = mBase + mf * 16 + g + half * 8;
            int m  = mt * BM + mloc;
            int kb = m / J_;
            int j  = m - kb * J_;
            int rowOff = ((kb * O_ + o) * J_ + j) * DIM;
            int selv = g_sel[j];
            #pragma unroll
            for (int nf = 0; nf < 4; nf++) {
                int n = nt * BN + nBase + nf * 8 + t4 * 2;
                float v0, v1;
                if (selv) {
                    v0 = acc[mf][nf][half * 2 + 0] * SCALE_F + bRow[n];
                    v1 = acc[mf][nf][half * 2 + 1] * SCALE_F + bRow[n + 1];
                } else {
                    v0 = x[rowOff + n];
                    v1 = x[rowOff + n + 1];
                }
                *reinterpret_cast<float2*>(out + rowOff + n) = make_float2(v0, v1);
            }
        }
    }
}

extern "C" void kernel_launch(void* const* d_in, const int* in_sizes, int n_in,
                              void* d_out, int out_size) {
    const float* x   = (const float*)d_in[0];
    const float* W   = (const float*)d_in[1];
    const float* b   = (const float*)d_in[2];
    const int*   idx = (const int*)d_in[3];
    float* out = (float*)d_out;

    prep_kernel<<<512, 256>>>(W, idx, in_sizes[3]);

    cudaFuncSetAttribute(dirnet_gemm_kernel,
                         cudaFuncAttributeMaxDynamicSharedMemorySize, SMEM_BYTES);

    dim3 grid(DIM / BN, M_TOTAL / BM, O_);
    dirnet_gemm_kernel<<<grid, NTHREADS, SMEM_BYTES>>>(x, b, out);
}